// round 7
// baseline (speedup 1.0000x reference)
#include <cuda_runtime.h>
#include <math.h>

#define IN_DIM 128
#define HID    64
#define HID4   16
#define NMAX   50176
#define EMAX   800256
#define XS_STRIDE 130
#define DEG_SCALE 1048576.0f          // 2^20 fixed-point for weighted degree

// ---------------- device scratch (no allocations allowed) -----------------
// Self-restoring invariant: d_degcnt, d_cnt, d_total are zero at the START
// of every kernel_launch call (zero-init on first call; last consumer resets).
__device__ unsigned long long d_degcnt[NMAX]; // {cnt:24 | deg_fixed:40}
__device__ int   d_cnt [NMAX];
__device__ float d_dinv[NMAX];
__device__ int   d_start[NMAX];
__device__ int   d_cursor[NMAX];
__device__ int   d_total;
__device__ int2  d_csr[EMAX];                 // {src, ew bits}, grouped by dst
__device__ float d_g  [(size_t)NMAX * HID];   // (x @ W1) * dinv[row]
__device__ float d_g2 [NMAX];                 // (relu(h1) @ W2) * dinv[row]

// -------- edge-index width detection (int64 vs int32) ---------------------
__device__ __forceinline__ bool is_i64(const int* ei) {
    return (ei[1] | ei[3] | ei[5] | ei[7]) == 0;
}
__device__ __forceinline__ void load_edge(const int* ei, int E, int e,
                                          bool i64, int& s, int& d) {
    if (i64) {
        const long long* p = (const long long*)ei;
        s = (int)p[e]; d = (int)p[E + e];
    } else {
        s = ei[e]; d = ei[E + e];
    }
}

// ======== K1: count — 4 edges/thread, independent u64 atomics ==============
__global__ void k_count(const int* __restrict__ ei,
                        const float* __restrict__ ew, int E) {
    int t  = blockIdx.x * blockDim.x + threadIdx.x;
    int e0 = t << 2;
    if (e0 >= E) return;
    bool i64 = is_i64(ei);
    int m = E - e0; if (m > 4) m = 4;

    int   d[4]; float w[4];
    #pragma unroll
    for (int i = 0; i < 4; i++) {
        if (i < m) {
            int s;
            load_edge(ei, E, e0 + i, i64, s, d[i]);
            (void)s;
            w[i] = ew[e0 + i];
        }
    }
    #pragma unroll
    for (int i = 0; i < 4; i++) {
        if (i < m) {
            unsigned long long enc = (1ULL << 40) |
                (unsigned long long)__float2uint_rn(w[i] * DEG_SCALE);
            atomicAdd(&d_degcnt[d[i]], enc);
        }
    }
}

// ======== K2: bump-alloc row starts + dinv; reset degcnt ===================
__global__ void k_alloc(int N) {
    int n = blockIdx.x * blockDim.x + threadIdx.x;
    if (n >= N) return;
    unsigned long long pc = d_degcnt[n];
    int   cnt = (int)(pc >> 40);
    float deg = (float)(pc & ((1ULL << 40) - 1)) * (1.0f / DEG_SCALE);
    int start = atomicAdd(&d_total, cnt);
    d_cnt[n]    = cnt;
    d_start[n]  = start;
    d_cursor[n] = start;
    d_dinv[n]   = rsqrtf(1.0f + deg);     // self-loop weight 1 => deg >= 1
    d_degcnt[n] = 0ULL;                   // restore for next replay
}

// ======== K3: GEMM g = (x @ W1) * dinv, f32x2 FFMA2 ========================
__device__ __forceinline__ unsigned long long pack2(float a, float b) {
    unsigned long long r;
    asm("mov.b64 %0, {%1, %2};" : "=l"(r) : "f"(a), "f"(b));
    return r;
}
__device__ __forceinline__ void fma2(unsigned long long& d,
                                     unsigned long long a, unsigned long long b) {
    asm("fma.rn.f32x2 %0, %1, %2, %0;" : "+l"(d) : "l"(a), "l"(b));
}
__device__ __forceinline__ void unpack2(unsigned long long v, float& a, float& b) {
    asm("mov.b64 {%0, %1}, %2;" : "=f"(a), "=f"(b) : "l"(v));
}

extern __shared__ float smem_dyn[];
#define GEMM_SMEM ((IN_DIM * HID + IN_DIM * XS_STRIDE) * 4)

__global__ void __launch_bounds__(128, 2)
k_gemm(const float* __restrict__ x, const float* __restrict__ W1, int N) {
    float* Ws = smem_dyn;                       // [128][64]
    float* xs = smem_dyn + IN_DIM * HID;        // [128][XS_STRIDE]
    int tid = threadIdx.x;
    int row0 = blockIdx.x * 128;

    #pragma unroll
    for (int i = 0; i < 16; i++)
        ((float4*)Ws)[tid + i * 128] = ((const float4*)W1)[tid + i * 128];

    #pragma unroll
    for (int i = 0; i < 32; i++) {
        int idx = tid + i * 128;
        int r   = idx >> 5;
        int k4  = idx & 31;
        float4 v = make_float4(0.f, 0.f, 0.f, 0.f);
        int row = row0 + r;
        if (row < N) v = ((const float4*)x)[(size_t)row * 32 + k4];
        float2* p = (float2*)&xs[r * XS_STRIDE + 4 * k4];
        p[0] = make_float2(v.x, v.y);
        p[1] = make_float2(v.z, v.w);
    }
    __syncthreads();

    int cg = tid & 7;       // 8 col groups x 8 cols
    int rg = tid >> 3;      // 16 row groups; thread rows: rg + 16*j
    unsigned long long acc[8][4];
    #pragma unroll
    for (int j = 0; j < 8; j++)
        #pragma unroll
        for (int p = 0; p < 4; p++) acc[j][p] = 0ULL;

    #pragma unroll 2
    for (int k = 0; k < IN_DIM; k++) {
        const unsigned long long* wp =
            (const unsigned long long*)&Ws[k * HID + 8 * cg];
        unsigned long long w0 = wp[0], w1 = wp[1], w2 = wp[2], w3 = wp[3];
        #pragma unroll
        for (int j = 0; j < 8; j++) {
            float xv = xs[(rg + 16 * j) * XS_STRIDE + k];
            unsigned long long xx = pack2(xv, xv);
            fma2(acc[j][0], xx, w0);
            fma2(acc[j][1], xx, w1);
            fma2(acc[j][2], xx, w2);
            fma2(acc[j][3], xx, w3);
        }
    }

    #pragma unroll
    for (int j = 0; j < 8; j++) {
        int row = row0 + rg + 16 * j;
        if (row < N) {
            float di = d_dinv[row];
            float2* dst = (float2*)&d_g[(size_t)row * HID + 8 * cg];
            #pragma unroll
            for (int p = 0; p < 4; p++) {
                float a, b; unpack2(acc[j][p], a, b);
                dst[p] = make_float2(di * a, di * b);
            }
        }
    }
}

// ======== K4: fill CSR — 4 edges/thread, independent atomic chains =========
__global__ void k_fill(const int* __restrict__ ei,
                       const float* __restrict__ ew, int E) {
    int t  = blockIdx.x * blockDim.x + threadIdx.x;
    int e0 = t << 2;
    if (e0 >= E) return;
    bool i64 = is_i64(ei);
    int m = E - e0; if (m > 4) m = 4;

    int s[4], d[4]; float w[4];
    #pragma unroll
    for (int i = 0; i < 4; i++) {
        if (i < m) {
            load_edge(ei, E, e0 + i, i64, s[i], d[i]);
            w[i] = ew[e0 + i];
        }
    }
    int slot[4];
    #pragma unroll
    for (int i = 0; i < 4; i++)
        if (i < m) slot[i] = atomicAdd(&d_cursor[d[i]], 1);
    #pragma unroll
    for (int i = 0; i < 4; i++)
        if (i < m) d_csr[slot[i]] = make_int2(s[i], __float_as_int(w[i]));
}

// ======== K5: layer-1 gather + bias + ReLU + @W2, fused ====================
// 16 threads per node, thread c owns float4 column c.
__global__ __launch_bounds__(256)
void k_agg1(const float* __restrict__ b1, const float* __restrict__ W2, int N) {
    int t = blockIdx.x * blockDim.x + threadIdx.x;
    int n = t >> 4;
    int c = t & 15;
    bool valid = (n < N);
    if (!valid) n = 0;

    int st  = d_start[n];
    int cnt = d_cnt[n];
    const float4* g4 = (const float4*)d_g;
    float4 acc = g4[(size_t)n * HID4 + c];          // self-loop term

    int j = 0;
    for (; j + 4 <= cnt; j += 4) {
        int2 e0 = d_csr[st + j];
        int2 e1 = d_csr[st + j + 1];
        int2 e2 = d_csr[st + j + 2];
        int2 e3 = d_csr[st + j + 3];
        float4 v0 = g4[(size_t)e0.x * HID4 + c];
        float4 v1 = g4[(size_t)e1.x * HID4 + c];
        float4 v2 = g4[(size_t)e2.x * HID4 + c];
        float4 v3 = g4[(size_t)e3.x * HID4 + c];
        float w0 = __int_as_float(e0.y), w1 = __int_as_float(e1.y);
        float w2 = __int_as_float(e2.y), w3 = __int_as_float(e3.y);
        acc.x = fmaf(w0, v0.x, fmaf(w1, v1.x, fmaf(w2, v2.x, fmaf(w3, v3.x, acc.x))));
        acc.y = fmaf(w0, v0.y, fmaf(w1, v1.y, fmaf(w2, v2.y, fmaf(w3, v3.y, acc.y))));
        acc.z = fmaf(w0, v0.z, fmaf(w1, v1.z, fmaf(w2, v2.z, fmaf(w3, v3.z, acc.z))));
        acc.w = fmaf(w0, v0.w, fmaf(w1, v1.w, fmaf(w2, v2.w, fmaf(w3, v3.w, acc.w))));
    }
    for (; j < cnt; j++) {
        int2 e = d_csr[st + j];
        float4 v = g4[(size_t)e.x * HID4 + c];
        float w = __int_as_float(e.y);
        acc.x = fmaf(w, v.x, acc.x);
        acc.y = fmaf(w, v.y, acc.y);
        acc.z = fmaf(w, v.z, acc.z);
        acc.w = fmaf(w, v.w, acc.w);
    }

    float di = d_dinv[n];
    float4 bb = ((const float4*)b1)[c];
    float4 v;
    v.x = fmaxf(fmaf(di, acc.x, bb.x), 0.f);
    v.y = fmaxf(fmaf(di, acc.y, bb.y), 0.f);
    v.z = fmaxf(fmaf(di, acc.z, bb.z), 0.f);
    v.w = fmaxf(fmaf(di, acc.w, bb.w), 0.f);
    float4 w2 = ((const float4*)W2)[c];
    float p = v.x * w2.x + v.y * w2.y + v.z * w2.z + v.w * w2.w;
    p += __shfl_xor_sync(0xffffffffu, p, 8);
    p += __shfl_xor_sync(0xffffffffu, p, 4);
    p += __shfl_xor_sync(0xffffffffu, p, 2);
    p += __shfl_xor_sync(0xffffffffu, p, 1);
    if (valid && c == 0) d_g2[n] = p * di;
}

// ======== K6: layer-2 gather + sigmoid + output; resets ====================
// 8 threads per node (4 nodes per warp).
__global__ void k_agg2(const float* __restrict__ b2, float* __restrict__ out, int N) {
    int t = blockIdx.x * blockDim.x + threadIdx.x;
    if (t == 0) d_total = 0;                  // restore for next replay
    int n    = t >> 3;
    int lane = t & 7;
    if (n >= N) return;                       // warp-uniform (N*8 % 32 == 0)
    int st  = d_start[n];
    int cnt = d_cnt[n];
    float acc = 0.f;
    for (int j = lane; j < cnt; j += 8) {
        int2 e = d_csr[st + j];
        acc += __int_as_float(e.y) * d_g2[e.x];
    }
    acc += __shfl_xor_sync(0xffffffffu, acc, 4);
    acc += __shfl_xor_sync(0xffffffffu, acc, 2);
    acc += __shfl_xor_sync(0xffffffffu, acc, 1);
    if (lane == 0) {
        float tt = fmaf(d_dinv[n], acc + d_g2[n], b2[0]);
        out[n] = 1.0f / (1.0f + expf(-tt));
        d_cnt[n] = 0;                         // restore for next replay
    }
}

// ---------------- launcher --------------------------------------------------
extern "C" void kernel_launch(void* const* d_in, const int* in_sizes, int n_in,
                              void* d_out, int out_size) {
    const float* x  = (const float*)d_in[0];
    const int*   ei = (const int*)d_in[1];
    const float* ew = (const float*)d_in[2];
    const float* W1 = (const float*)d_in[3];
    const float* b1 = (const float*)d_in[4];
    const float* W2 = (const float*)d_in[5];
    const float* b2 = (const float*)d_in[6];
    float* out = (float*)d_out;

    int N = in_sizes[0] / IN_DIM;   // 50000
    int E = in_sizes[2];            // 800000

    cudaFuncSetAttribute(k_gemm, cudaFuncAttributeMaxDynamicSharedMemorySize,
                         GEMM_SMEM);

    int eq = (E + 3) / 4;
    k_count<<<(eq + 255) / 256, 256>>>(ei, ew, E);
    k_alloc<<<(N + 255) / 256, 256>>>(N);
    k_gemm <<<(N + 127) / 128, 128, GEMM_SMEM>>>(x, W1, N);
    k_fill <<<(eq + 255) / 256, 256>>>(ei, ew, E);
    k_agg1 <<<(N * 16 + 255) / 256, 256>>>(b1, W2, N);
    k_agg2 <<<(N * 8 + 255) / 256, 256>>>(b2, out, N);
}

// round 8
// speedup vs baseline: 1.0566x; 1.0566x over previous
#include <cuda_runtime.h>
#include <math.h>

#define IN_DIM 128
#define HID    64
#define HID4   16
#define NMAX   50176
#define EMAX   800256
#define XS_STRIDE 130
#define DEG_SCALE 1048576.0f          // 2^20 fixed-point for weighted degree

// ---------------- device scratch (no allocations allowed) -----------------
// Self-restoring invariant: d_degcnt, d_cnt, d_total are zero at the START
// of every kernel_launch call (zero-init on first call; last consumer resets).
__device__ unsigned long long d_degcnt[NMAX]; // {cnt:24 | deg_fixed:40}
__device__ int   d_cnt [NMAX];
__device__ float d_dinv[NMAX];
__device__ int   d_start[NMAX];
__device__ int   d_rank[EMAX];                // edge's rank within its dst row
__device__ int   d_total;
__device__ int2  d_csr[EMAX];                 // {src, ew bits}, grouped by dst
__device__ float d_g  [(size_t)NMAX * HID];   // (x @ W1) * dinv[row]
__device__ float d_g2 [NMAX];                 // (relu(h1) @ W2) * dinv[row]

// -------- edge-index width detection (int64 vs int32) ---------------------
__device__ __forceinline__ bool is_i64(const int* ei) {
    return (ei[1] | ei[3] | ei[5] | ei[7]) == 0;
}
__device__ __forceinline__ void load_edge(const int* ei, int E, int e,
                                          bool i64, int& s, int& d) {
    if (i64) {
        const long long* p = (const long long*)ei;
        s = (int)p[e]; d = (int)p[E + e];
    } else {
        s = ei[e]; d = ei[E + e];
    }
}

// ======== K1: count — 1 u64 atomic per edge; returned cnt = slot rank ======
__global__ void k_count(const int* __restrict__ ei,
                        const float* __restrict__ ew, int E) {
    int e = blockIdx.x * blockDim.x + threadIdx.x;
    if (e >= E) return;
    bool i64 = is_i64(ei);
    int d;
    if (i64) {
        d = (int)((const long long*)ei)[E + e];
    } else {
        d = ei[E + e];
    }
    unsigned long long enc = (1ULL << 40) |
        (unsigned long long)__float2uint_rn(ew[e] * DEG_SCALE);
    unsigned long long prev = atomicAdd(&d_degcnt[d], enc);
    d_rank[e] = (int)(prev >> 40);
}

// ======== K2: bump-alloc row starts + dinv; reset degcnt ===================
__global__ void k_alloc(int N) {
    int n = blockIdx.x * blockDim.x + threadIdx.x;
    if (n >= N) return;
    unsigned long long pc = d_degcnt[n];
    int   cnt = (int)(pc >> 40);
    float deg = (float)(pc & ((1ULL << 40) - 1)) * (1.0f / DEG_SCALE);
    int start = atomicAdd(&d_total, cnt);
    d_cnt[n]    = cnt;
    d_start[n]  = start;
    d_dinv[n]   = rsqrtf(1.0f + deg);     // self-loop weight 1 => deg >= 1
    d_degcnt[n] = 0ULL;                   // restore for next replay
}

// ======== K3: GEMM g = (x @ W1) * dinv, f32x2 FFMA2 ========================
__device__ __forceinline__ unsigned long long pack2(float a, float b) {
    unsigned long long r;
    asm("mov.b64 %0, {%1, %2};" : "=l"(r) : "f"(a), "f"(b));
    return r;
}
__device__ __forceinline__ void fma2(unsigned long long& d,
                                     unsigned long long a, unsigned long long b) {
    asm("fma.rn.f32x2 %0, %1, %2, %0;" : "+l"(d) : "l"(a), "l"(b));
}
__device__ __forceinline__ void unpack2(unsigned long long v, float& a, float& b) {
    asm("mov.b64 {%0, %1}, %2;" : "=f"(a), "=f"(b) : "l"(v));
}

extern __shared__ float smem_dyn[];
#define GEMM_SMEM ((IN_DIM * HID + IN_DIM * XS_STRIDE) * 4)

__global__ void __launch_bounds__(128, 2)
k_gemm(const float* __restrict__ x, const float* __restrict__ W1, int N) {
    float* Ws = smem_dyn;                       // [128][64]
    float* xs = smem_dyn + IN_DIM * HID;        // [128][XS_STRIDE]
    int tid = threadIdx.x;
    int row0 = blockIdx.x * 128;

    #pragma unroll
    for (int i = 0; i < 16; i++)
        ((float4*)Ws)[tid + i * 128] = ((const float4*)W1)[tid + i * 128];

    #pragma unroll
    for (int i = 0; i < 32; i++) {
        int idx = tid + i * 128;
        int r   = idx >> 5;
        int k4  = idx & 31;
        float4 v = make_float4(0.f, 0.f, 0.f, 0.f);
        int row = row0 + r;
        if (row < N) v = ((const float4*)x)[(size_t)row * 32 + k4];
        float2* p = (float2*)&xs[r * XS_STRIDE + 4 * k4];
        p[0] = make_float2(v.x, v.y);
        p[1] = make_float2(v.z, v.w);
    }
    __syncthreads();

    int cg = tid & 7;       // 8 col groups x 8 cols
    int rg = tid >> 3;      // 16 row groups; thread rows: rg + 16*j
    unsigned long long acc[8][4];
    #pragma unroll
    for (int j = 0; j < 8; j++)
        #pragma unroll
        for (int p = 0; p < 4; p++) acc[j][p] = 0ULL;

    #pragma unroll 2
    for (int k = 0; k < IN_DIM; k++) {
        const unsigned long long* wp =
            (const unsigned long long*)&Ws[k * HID + 8 * cg];
        unsigned long long w0 = wp[0], w1 = wp[1], w2 = wp[2], w3 = wp[3];
        #pragma unroll
        for (int j = 0; j < 8; j++) {
            float xv = xs[(rg + 16 * j) * XS_STRIDE + k];
            unsigned long long xx = pack2(xv, xv);
            fma2(acc[j][0], xx, w0);
            fma2(acc[j][1], xx, w1);
            fma2(acc[j][2], xx, w2);
            fma2(acc[j][3], xx, w3);
        }
    }

    #pragma unroll
    for (int j = 0; j < 8; j++) {
        int row = row0 + rg + 16 * j;
        if (row < N) {
            float di = d_dinv[row];
            float2* dst = (float2*)&d_g[(size_t)row * HID + 8 * cg];
            #pragma unroll
            for (int p = 0; p < 4; p++) {
                float a, b; unpack2(acc[j][p], a, b);
                dst[p] = make_float2(di * a, di * b);
            }
        }
    }
}

// ======== K4: fill CSR — NO atomics: slot = start[dst] + rank[e] ===========
__global__ void k_fill(const int* __restrict__ ei,
                       const float* __restrict__ ew, int E) {
    int e = blockIdx.x * blockDim.x + threadIdx.x;
    if (e >= E) return;
    bool i64 = is_i64(ei);
    int s, d; load_edge(ei, E, e, i64, s, d);
    int slot = d_start[d] + d_rank[e];
    d_csr[slot] = make_int2(s, __float_as_int(ew[e]));
}

// ======== K5: layer-1 gather + bias + ReLU + @W2, fused ====================
// 16 threads per node, thread c owns float4 column c.
__global__ __launch_bounds__(256)
void k_agg1(const float* __restrict__ b1, const float* __restrict__ W2, int N) {
    int t = blockIdx.x * blockDim.x + threadIdx.x;
    int n = t >> 4;
    int c = t & 15;
    bool valid = (n < N);
    if (!valid) n = 0;

    int st  = d_start[n];
    int cnt = d_cnt[n];
    const float4* g4 = (const float4*)d_g;
    float4 acc = g4[(size_t)n * HID4 + c];          // self-loop term

    int j = 0;
    for (; j + 4 <= cnt; j += 4) {
        int2 e0 = d_csr[st + j];
        int2 e1 = d_csr[st + j + 1];
        int2 e2 = d_csr[st + j + 2];
        int2 e3 = d_csr[st + j + 3];
        float4 v0 = g4[(size_t)e0.x * HID4 + c];
        float4 v1 = g4[(size_t)e1.x * HID4 + c];
        float4 v2 = g4[(size_t)e2.x * HID4 + c];
        float4 v3 = g4[(size_t)e3.x * HID4 + c];
        float w0 = __int_as_float(e0.y), w1 = __int_as_float(e1.y);
        float w2 = __int_as_float(e2.y), w3 = __int_as_float(e3.y);
        acc.x = fmaf(w0, v0.x, fmaf(w1, v1.x, fmaf(w2, v2.x, fmaf(w3, v3.x, acc.x))));
        acc.y = fmaf(w0, v0.y, fmaf(w1, v1.y, fmaf(w2, v2.y, fmaf(w3, v3.y, acc.y))));
        acc.z = fmaf(w0, v0.z, fmaf(w1, v1.z, fmaf(w2, v2.z, fmaf(w3, v3.z, acc.z))));
        acc.w = fmaf(w0, v0.w, fmaf(w1, v1.w, fmaf(w2, v2.w, fmaf(w3, v3.w, acc.w))));
    }
    for (; j < cnt; j++) {
        int2 e = d_csr[st + j];
        float4 v = g4[(size_t)e.x * HID4 + c];
        float w = __int_as_float(e.y);
        acc.x = fmaf(w, v.x, acc.x);
        acc.y = fmaf(w, v.y, acc.y);
        acc.z = fmaf(w, v.z, acc.z);
        acc.w = fmaf(w, v.w, acc.w);
    }

    float di = d_dinv[n];
    float4 bb = ((const float4*)b1)[c];
    float4 v;
    v.x = fmaxf(fmaf(di, acc.x, bb.x), 0.f);
    v.y = fmaxf(fmaf(di, acc.y, bb.y), 0.f);
    v.z = fmaxf(fmaf(di, acc.z, bb.z), 0.f);
    v.w = fmaxf(fmaf(di, acc.w, bb.w), 0.f);
    float4 w2 = ((const float4*)W2)[c];
    float p = v.x * w2.x + v.y * w2.y + v.z * w2.z + v.w * w2.w;
    p += __shfl_xor_sync(0xffffffffu, p, 8);
    p += __shfl_xor_sync(0xffffffffu, p, 4);
    p += __shfl_xor_sync(0xffffffffu, p, 2);
    p += __shfl_xor_sync(0xffffffffu, p, 1);
    if (valid && c == 0) d_g2[n] = p * di;
}

// ======== K6: layer-2 gather + sigmoid + output; resets ====================
// 8 threads per node (4 nodes per warp).
__global__ void k_agg2(const float* __restrict__ b2, float* __restrict__ out, int N) {
    int t = blockIdx.x * blockDim.x + threadIdx.x;
    if (t == 0) d_total = 0;                  // restore for next replay
    int n    = t >> 3;
    int lane = t & 7;
    if (n >= N) return;                       // warp-uniform (N*8 % 32 == 0)
    int st  = d_start[n];
    int cnt = d_cnt[n];
    float acc = 0.f;
    for (int j = lane; j < cnt; j += 8) {
        int2 e = d_csr[st + j];
        acc += __int_as_float(e.y) * d_g2[e.x];
    }
    acc += __shfl_xor_sync(0xffffffffu, acc, 4);
    acc += __shfl_xor_sync(0xffffffffu, acc, 2);
    acc += __shfl_xor_sync(0xffffffffu, acc, 1);
    if (lane == 0) {
        float tt = fmaf(d_dinv[n], acc + d_g2[n], b2[0]);
        out[n] = 1.0f / (1.0f + expf(-tt));
        d_cnt[n] = 0;                         // restore for next replay
    }
}

// ---------------- launcher --------------------------------------------------
extern "C" void kernel_launch(void* const* d_in, const int* in_sizes, int n_in,
                              void* d_out, int out_size) {
    const float* x  = (const float*)d_in[0];
    const int*   ei = (const int*)d_in[1];
    const float* ew = (const float*)d_in[2];
    const float* W1 = (const float*)d_in[3];
    const float* b1 = (const float*)d_in[4];
    const float* W2 = (const float*)d_in[5];
    const float* b2 = (const float*)d_in[6];
    float* out = (float*)d_out;

    int N = in_sizes[0] / IN_DIM;   // 50000
    int E = in_sizes[2];            // 800000

    cudaFuncSetAttribute(k_gemm, cudaFuncAttributeMaxDynamicSharedMemorySize,
                         GEMM_SMEM);

    k_count<<<(E + 255) / 256, 256>>>(ei, ew, E);
    k_alloc<<<(N + 255) / 256, 256>>>(N);
    k_gemm <<<(N + 127) / 128, 128, GEMM_SMEM>>>(x, W1, N);
    k_fill <<<(E + 255) / 256, 256>>>(ei, ew, E);
    k_agg1 <<<(N * 16 + 255) / 256, 256>>>(b1, W2, N);
    k_agg2 <<<(N * 8 + 255) / 256, 256>>>(b2, out, N);
}